// round 2
// baseline (speedup 1.0000x reference)
#include <cuda_runtime.h>
#include <cstdint>

// Problem shape (fixed by the reference setup_inputs)
constexpr int B = 2, H = 16, S = 2048, D = 64;
constexpr int NT = 128;  // threads per CTA

__global__ __launch_bounds__(NT)
void sdpa_kernel(const float* __restrict__ q,
                 const float* __restrict__ k,
                 const float* __restrict__ v,
                 const uint32_t* __restrict__ mask,   // dtype unknown: probed below
                 float* __restrict__ out,    // [B,H,S,D]
                 float* __restrict__ wout)   // [B,H,S,S]
{
    const int idx  = blockIdx.x;          // (b*H + h)*S + qrow
    const int qrow = idx & (S - 1);
    const int bh   = idx >> 11;           // S = 2048 = 2^11
    const int b    = bh >> 4;             // H = 16

    __shared__ float w[S];                // logits -> exp -> normalized weights
    __shared__ float qs[D];
    __shared__ float red[NT / 32];
    __shared__ float part[2][D];
    __shared__ int   smode;               // 1 = 4-byte mask elems, 0 = 1-byte

    const int tid  = threadIdx.x;
    const int lane = tid & 31;
    const int wid  = tid >> 5;

    // ---- probe mask element width (values are only 0/1 or 0.0f/1.0f) ----
    if (tid == 0) {
        int wide = 1;                      // default: 4-byte (int32, all words 0/1)
        for (int i = 0; i < 256; i++) {
            uint32_t x = mask[i];
            if (x > 1u) { wide = (x == 0x3F800000u) ? 1 : 0; break; }
        }
        smode = wide;
    }

    // Stage scaled Q row into smem, then into registers
    const float* qptr = q + ((size_t)bh * S + qrow) * D;
    if (tid < D) qs[tid] = qptr[tid] * 0.125f;   // 1/sqrt(64)
    __syncthreads();

    float qreg[D];
    #pragma unroll
    for (int i = 0; i < D; i++) qreg[i] = qs[i];

    const int wide = smode;
    const float* kbase = k + (size_t)bh * S * D;
    const size_t mbase = ((size_t)b * S + qrow) * S;
    const uint32_t*      mrow32 = mask + mbase;
    const unsigned char* mrow8  = reinterpret_cast<const unsigned char*>(mask) + mbase;

    // ---- QK^T + mask, track row max ----
    float lmax = -3.4e38f;
    #pragma unroll 1
    for (int j = tid; j < S; j += NT) {
        const float4* krow = reinterpret_cast<const float4*>(kbase + (size_t)j * D);
        float a0 = 0.f, a1 = 0.f, a2 = 0.f, a3 = 0.f;
        #pragma unroll
        for (int d4 = 0; d4 < D / 4; d4++) {
            float4 kk = krow[d4];
            a0 += qreg[d4 * 4 + 0] * kk.x;
            a1 += qreg[d4 * 4 + 1] * kk.y;
            a2 += qreg[d4 * 4 + 2] * kk.z;
            a3 += qreg[d4 * 4 + 3] * kk.w;
        }
        float acc = (a0 + a1) + (a2 + a3);
        const bool m = wide ? (mrow32[j] != 0u) : (mrow8[j] != 0);
        if (m) acc = -1e-9f;           // faithful to reference: tiny fill, NOT -inf
        w[j] = acc;
        lmax = fmaxf(lmax, acc);
    }

    // block-reduce max
    #pragma unroll
    for (int o = 16; o; o >>= 1) lmax = fmaxf(lmax, __shfl_xor_sync(0xffffffffu, lmax, o));
    if (lane == 0) red[wid] = lmax;
    __syncthreads();
    const float gmax = fmaxf(fmaxf(red[0], red[1]), fmaxf(red[2], red[3]));

    // ---- exp + sum ----
    float lsum = 0.f;
    #pragma unroll 1
    for (int j = tid; j < S; j += NT) {
        float e = __expf(w[j] - gmax);
        w[j] = e;
        lsum += e;
    }
    #pragma unroll
    for (int o = 16; o; o >>= 1) lsum += __shfl_xor_sync(0xffffffffu, lsum, o);
    __syncthreads();                       // protect red reuse
    if (lane == 0) red[wid] = lsum;
    __syncthreads();
    const float inv = 1.f / (red[0] + red[1] + red[2] + red[3]);

    // ---- normalize, write weights (coalesced float4) ----
    float4* wrow = reinterpret_cast<float4*>(wout + ((size_t)bh * S + qrow) * S);
    float4* wsh  = reinterpret_cast<float4*>(w);
    #pragma unroll 1
    for (int j4 = tid; j4 < S / 4; j4 += NT) {
        float4 t = wsh[j4];
        t.x *= inv; t.y *= inv; t.z *= inv; t.w *= inv;
        wsh[j4]  = t;
        wrow[j4] = t;
    }
    __syncthreads();

    // ---- PV: out[d] = sum_j w[j] * v[j,d]; 2-way j split across 128 threads ----
    const float* vbase = v + (size_t)bh * S * D;
    const int d    = tid & (D - 1);
    const int half = tid >> 6;             // 0 or 1
    const int j0   = half * (S / 2);
    float acc = 0.f;
    #pragma unroll 4
    for (int j = j0; j < j0 + S / 2; j++) {
        acc += w[j] * vbase[(size_t)j * D + d];
    }
    part[half][d] = acc;
    __syncthreads();
    if (tid < D) {
        out[((size_t)bh * S + qrow) * D + tid] = part[0][tid] + part[1][tid];
    }
}

extern "C" void kernel_launch(void* const* d_in, const int* in_sizes, int n_in,
                              void* d_out, int out_size)
{
    const float* q = (const float*)d_in[0];
    const float* k = (const float*)d_in[1];
    const float* v = (const float*)d_in[2];
    const uint32_t* mask = (const uint32_t*)d_in[3];

    float* out  = (float*)d_out;                       // [B,H,S,D] first
    float* wout = out + (size_t)B * H * S * D;         // then [B,H,S,S] weights

    sdpa_kernel<<<B * H * S, NT>>>(q, k, v, mask, out, wout);
}

// round 3
// speedup vs baseline: 7.5006x; 7.5006x over previous
#include <cuda_runtime.h>
#include <cstdint>

constexpr int B = 2, H = 16, S = 2048, D = 64;
constexpr int TQ = 16;     // q rows per CTA
constexpr int TK = 64;     // k rows per smem tile
constexpr int NT = 256;    // threads per CTA
constexpr int WPAD = 2052; // padded logit row stride (floats): breaks bank conflicts, 16B-aligned

#define FMA2(d, a, b, c) asm("fma.rn.f32x2 %0,%1,%2,%3;" : "=l"(d) : "l"(a), "l"(b), "l"(c))
#define PACK2(d, x, y)   asm("mov.b64 %0,{%1,%2};" : "=l"(d) : "f"(x), "f"(y))
#define UNPK2(x, y, d)   asm("mov.b64 {%0,%1},%2;" : "=f"(x), "=f"(y) : "l"(d))

__global__ __launch_bounds__(NT, 1)
void sdpa_tiled(const float* __restrict__ q,
                const float* __restrict__ k,
                const float* __restrict__ v,
                const uint32_t* __restrict__ mask,
                float* __restrict__ out,    // [B,H,S,D]
                float* __restrict__ wout)   // [B,H,S,S]
{
    extern __shared__ float sm[];
    float* wsm = sm;                      // [TQ][WPAD]  logits
    float* ksh = sm + TQ * WPAD;          // [2][TK*D]   K tiles (aliased by PV partials later)

    __shared__ float rowinv[TQ];
    __shared__ int   smode;

    const int tid  = threadIdx.x;
    const int lane = tid & 31;
    const int wid  = tid >> 5;

    const int bx = blockIdx.x;
    const int bh = bx >> 7;               // S/TQ = 128 q-tiles per (b,h)
    const int q0 = (bx & 127) * TQ;
    const int b  = bh >> 4;               // H = 16

    // ---- probe mask element width (bool may arrive as int32 or bytes) ----
    if (tid == 0) {
        int wide = 1;
        for (int i = 0; i < 256; i++) {
            uint32_t x = mask[i];
            if (x > 1u) { wide = (x == 0x3F800000u) ? 1 : 0; break; }
        }
        smode = wide;
    }

    // ---- load this lane's q row (scaled), packed as f32x2 ----
    const int row = lane & 15;
    const int jsel = lane >> 4;
    const float* qptr = q + ((size_t)bh * S + q0 + row) * D;
    unsigned long long q2[32];
    #pragma unroll
    for (int t = 0; t < 16; t++) {
        float4 f = reinterpret_cast<const float4*>(qptr)[t];
        f.x *= 0.125f; f.y *= 0.125f; f.z *= 0.125f; f.w *= 0.125f;
        PACK2(q2[2 * t],     f.x, f.y);
        PACK2(q2[2 * t + 1], f.z, f.w);
    }

    // ================= QK^T : logits -> smem =================
    const float* kbase = k + (size_t)bh * S * D;
    float4 pf[4];
    #pragma unroll
    for (int i = 0; i < 4; i++)
        pf[i] = reinterpret_cast<const float4*>(kbase)[i * 256 + tid];
    #pragma unroll
    for (int i = 0; i < 4; i++)
        reinterpret_cast<float4*>(ksh)[i * 256 + tid] = pf[i];
    __syncthreads();

    constexpr int NTILE = S / TK;  // 32
    for (int jt = 0; jt < NTILE; jt++) {
        const int buf = jt & 1;
        if (jt < NTILE - 1) {
            const float4* src = reinterpret_cast<const float4*>(kbase + (size_t)(jt + 1) * TK * D);
            #pragma unroll
            for (int i = 0; i < 4; i++) pf[i] = src[i * 256 + tid];
        }
        const float* kb = ksh + buf * (TK * D);
        #pragma unroll
        for (int it = 0; it < 4; it++) {
            const int jl = it * 16 + wid * 2 + jsel;
            const ulonglong2* kr = reinterpret_cast<const ulonglong2*>(kb + jl * D);
            unsigned long long a0 = 0ull, a1 = 0ull, a2 = 0ull, a3 = 0ull;
            #pragma unroll
            for (int t = 0; t < 16; t += 2) {
                ulonglong2 ka = kr[t];
                ulonglong2 kc = kr[t + 1];
                FMA2(a0, q2[2 * t],     ka.x, a0);
                FMA2(a1, q2[2 * t + 1], ka.y, a1);
                FMA2(a2, q2[2 * t + 2], kc.x, a2);
                FMA2(a3, q2[2 * t + 3], kc.y, a3);
            }
            float x0, x1, x2, x3, x4, x5, x6, x7;
            UNPK2(x0, x1, a0); UNPK2(x2, x3, a1);
            UNPK2(x4, x5, a2); UNPK2(x6, x7, a3);
            wsm[row * WPAD + jt * TK + jl] = ((x0 + x1) + (x2 + x3)) + ((x4 + x5) + (x6 + x7));
        }
        if (jt < NTILE - 1) {
            float* dst = ksh + (1 - buf) * (TK * D);
            #pragma unroll
            for (int i = 0; i < 4; i++)
                reinterpret_cast<float4*>(dst)[i * 256 + tid] = pf[i];
        }
        __syncthreads();
    }

    // ============ softmax sweeps: each warp owns rows 2w, 2w+1 ============
    const int wide = smode;
    #pragma unroll
    for (int rr = 0; rr < 2; rr++) {
        const int r = wid * 2 + rr;
        float* wr = wsm + r * WPAD;
        float4* wr4 = reinterpret_cast<float4*>(wr);

        // pass 1: mask + row max
        float mx = -3.4e38f;
        if (wide) {
            const int4* m4 = reinterpret_cast<const int4*>(mask + ((size_t)b * S + q0 + r) * S);
            for (int t = lane; t < S / 4; t += 32) {
                float4 x = wr4[t];
                int4 m = m4[t];
                if (m.x) x.x = -1e-9f;
                if (m.y) x.y = -1e-9f;
                if (m.z) x.z = -1e-9f;
                if (m.w) x.w = -1e-9f;
                mx = fmaxf(mx, fmaxf(fmaxf(x.x, x.y), fmaxf(x.z, x.w)));
                wr4[t] = x;
            }
        } else {
            const uchar4* m4 = reinterpret_cast<const uchar4*>(
                reinterpret_cast<const unsigned char*>(mask) + ((size_t)b * S + q0 + r) * S);
            for (int t = lane; t < S / 4; t += 32) {
                float4 x = wr4[t];
                uchar4 m = m4[t];
                if (m.x) x.x = -1e-9f;
                if (m.y) x.y = -1e-9f;
                if (m.z) x.z = -1e-9f;
                if (m.w) x.w = -1e-9f;
                mx = fmaxf(mx, fmaxf(fmaxf(x.x, x.y), fmaxf(x.z, x.w)));
                wr4[t] = x;
            }
        }
        #pragma unroll
        for (int o = 16; o; o >>= 1) mx = fmaxf(mx, __shfl_xor_sync(0xffffffffu, mx, o));

        // pass 2: exp + sum (store unnormalized exp)
        float sum = 0.f;
        for (int t = lane; t < S / 4; t += 32) {
            float4 x = wr4[t];
            x.x = __expf(x.x - mx); x.y = __expf(x.y - mx);
            x.z = __expf(x.z - mx); x.w = __expf(x.w - mx);
            sum += (x.x + x.y) + (x.z + x.w);
            wr4[t] = x;
        }
        #pragma unroll
        for (int o = 16; o; o >>= 1) sum += __shfl_xor_sync(0xffffffffu, sum, o);
        const float inv = 1.f / sum;
        if (lane == 0) rowinv[r] = inv;

        // pass 3: normalized weights -> gmem (coalesced float4)
        float4* go = reinterpret_cast<float4*>(wout + ((size_t)bh * S + q0 + r) * S);
        for (int t = lane; t < S / 4; t += 32) {
            float4 x = wr4[t];
            x.x *= inv; x.y *= inv; x.z *= inv; x.w *= inv;
            go[t] = x;
        }
    }
    __syncthreads();

    // ================= PV : out = softmax(W) @ V =================
    // thread -> (d4: float4 of d, rq: 4-row block, jq: j quarter)
    {
        const int d4 = tid & 15;
        const int rq = (tid >> 4) & 3;
        const int jq = tid >> 6;
        const ulonglong2* vb = reinterpret_cast<const ulonglong2*>(v + (size_t)bh * S * D);

        unsigned long long acc[8];
        #pragma unroll
        for (int i = 0; i < 8; i++) acc[i] = 0ull;

        const float* w0 = wsm + (rq * 4 + 0) * WPAD;
        const float* w1 = wsm + (rq * 4 + 1) * WPAD;
        const float* w2 = wsm + (rq * 4 + 2) * WPAD;
        const float* w3 = wsm + (rq * 4 + 3) * WPAD;

        const int jend = jq * 512 + 512;
        for (int j = jq * 512; j < jend; j += 4) {
            float wa[4], wb[4], wc[4], wd[4];
            *reinterpret_cast<float4*>(wa) = *reinterpret_cast<const float4*>(w0 + j);
            *reinterpret_cast<float4*>(wb) = *reinterpret_cast<const float4*>(w1 + j);
            *reinterpret_cast<float4*>(wc) = *reinterpret_cast<const float4*>(w2 + j);
            *reinterpret_cast<float4*>(wd) = *reinterpret_cast<const float4*>(w3 + j);
            #pragma unroll
            for (int jj = 0; jj < 4; jj++) {
                ulonglong2 v2 = vb[(size_t)(j + jj) * 16 + d4];
                unsigned long long p;
                PACK2(p, wa[jj], wa[jj]); FMA2(acc[0], p, v2.x, acc[0]); FMA2(acc[1], p, v2.y, acc[1]);
                PACK2(p, wb[jj], wb[jj]); FMA2(acc[2], p, v2.x, acc[2]); FMA2(acc[3], p, v2.y, acc[3]);
                PACK2(p, wc[jj], wc[jj]); FMA2(acc[4], p, v2.x, acc[4]); FMA2(acc[5], p, v2.y, acc[5]);
                PACK2(p, wd[jj], wd[jj]); FMA2(acc[6], p, v2.x, acc[6]); FMA2(acc[7], p, v2.y, acc[7]);
            }
        }

        __syncthreads();   // ksh region is dead; reuse as PV partial buffer
        float4* pred = reinterpret_cast<float4*>(ksh);  // [4(jq)][16(row)][16(d4)] float4
        #pragma unroll
        for (int rr = 0; rr < 4; rr++) {
            float4 o;
            UNPK2(o.x, o.y, acc[2 * rr]);
            UNPK2(o.z, o.w, acc[2 * rr + 1]);
            pred[(jq * 16 + rq * 4 + rr) * 16 + d4] = o;
        }
    }
    __syncthreads();

    // cross-jq reduce + scale + write out
    {
        const int r  = tid >> 4;
        const int dd = tid & 15;
        const float4* pred = reinterpret_cast<const float4*>(ksh);
        float4 o = pred[(0 * 16 + r) * 16 + dd];
        #pragma unroll
        for (int jq = 1; jq < 4; jq++) {
            float4 p = pred[(jq * 16 + r) * 16 + dd];
            o.x += p.x; o.y += p.y; o.z += p.z; o.w += p.w;
        }
        const float inv = rowinv[r];
        o.x *= inv; o.y *= inv; o.z *= inv; o.w *= inv;
        reinterpret_cast<float4*>(out + ((size_t)bh * S + q0 + r) * D)[dd] = o;
    }
}

extern "C" void kernel_launch(void* const* d_in, const int* in_sizes, int n_in,
                              void* d_out, int out_size)
{
    const float* q = (const float*)d_in[0];
    const float* k = (const float*)d_in[1];
    const float* v = (const float*)d_in[2];
    const uint32_t* mask = (const uint32_t*)d_in[3];

    float* out  = (float*)d_out;
    float* wout = out + (size_t)B * H * S * D;

    constexpr int SMEM = (TQ * WPAD + 2 * TK * D) * 4;  // 164,096 B
    static bool configured = false;
    if (!configured) {
        cudaFuncSetAttribute(sdpa_tiled, cudaFuncAttributeMaxDynamicSharedMemorySize, SMEM);
        configured = true;
    }
    sdpa_tiled<<<B * H * (S / TQ), NT, SMEM>>>(q, k, v, mask, out, wout);
}